// round 1
// baseline (speedup 1.0000x reference)
#include <cuda_runtime.h>
#include <cstddef>

#define RLA_EPS 1e-6f

__device__ __forceinline__ float elu1(float x) {
    // elu(x) + 1  ==  x>0 ? x+1 : exp(x)
    return x > 0.0f ? x + 1.0f : __expf(x);
}

// One CTA per (b,n) pair. 256 threads.
// Phase 1: Q/K feature maps, Zi_new, block-reduced normalizer Z.
// Phase 2: stream Si tile [D, M] once as float4, rank-1 update, accumulate V.
__global__ __launch_bounds__(256, 8)
void rla_kernel(const float* __restrict__ q,
                const float* __restrict__ k,
                const float* __restrict__ v,
                const float* __restrict__ Si,
                const float* __restrict__ Zi,
                float* __restrict__ outV,    // [BN, M]
                float* __restrict__ outSi,   // [BN, D, M]
                float* __restrict__ outZi,   // [BN, D]
                int D, int M)
{
    const int bn  = blockIdx.x;
    const int tid = threadIdx.x;

    // D, M <= 1024 assumed for smem staging of Q/K (here D = 256)
    __shared__ float sQ[256];
    __shared__ float sK[256];
    __shared__ float sred[256];
    __shared__ float sZ;
    __shared__ float4 sacc[256];  // cross-d-group reduction buffer

    const size_t rowD = (size_t)bn * D;
    const size_t rowM = (size_t)bn * M;
    const size_t tile = (size_t)bn * D * M;

    // ---------------- Phase 1: feature maps + normalizer ----------------
    float part = 0.0f;
    for (int d = tid; d < D; d += blockDim.x) {
        float Qd = elu1(q[rowD + d]);
        float Kd = elu1(k[rowD + d]);
        float zn = Zi[rowD + d] + Kd;
        outZi[rowD + d] = zn;
        sQ[d] = Qd;
        sK[d] = Kd;
        part += Qd * zn;
    }
    sred[tid] = part;
    __syncthreads();
    #pragma unroll
    for (int s = 128; s > 0; s >>= 1) {
        if (tid < s) sred[tid] += sred[tid + s];
        __syncthreads();
    }
    if (tid == 0) sZ = 1.0f / (sred[0] + RLA_EPS);
    __syncthreads();
    const float Z = sZ;

    // ---------------- Phase 2: stream Si, rank-1 update, accumulate V ----
    const int M4   = M >> 2;       // float4 columns (M assumed %4 == 0)
    const int lane = tid & 63;     // m4 column within chunk
    const int ty   = tid >> 6;     // d-subgroup 0..3

    const float4* Si4 = (const float4*)(Si    + tile);
    float4*       So4 = (float4*)      (outSi + tile);
    const float4* v4p = (const float4*)(v     + rowM);
    float4*       V4  = (float4*)      (outV  + rowM);

    for (int m0 = 0; m0 < M4; m0 += 64) {
        const int m4 = m0 + lane;
        const bool act = (m4 < M4);

        float4 v4 = make_float4(0.f, 0.f, 0.f, 0.f);
        if (act) v4 = v4p[m4];

        float4 acc = make_float4(0.f, 0.f, 0.f, 0.f);

        if (act) {
            #pragma unroll 8
            for (int d = ty; d < D; d += 4) {
                const size_t idx = (size_t)d * M4 + m4;
                float4 s = __ldcs(&Si4[idx]);
                const float kd = sK[d];
                const float qd = sQ[d];
                s.x = fmaf(kd, v4.x, s.x);
                s.y = fmaf(kd, v4.y, s.y);
                s.z = fmaf(kd, v4.z, s.z);
                s.w = fmaf(kd, v4.w, s.w);
                __stcs(&So4[idx], s);
                acc.x = fmaf(qd, s.x, acc.x);
                acc.y = fmaf(qd, s.y, acc.y);
                acc.z = fmaf(qd, s.z, acc.z);
                acc.w = fmaf(qd, s.w, acc.w);
            }
        }

        sacc[tid] = acc;
        __syncthreads();
        if (ty == 0 && act) {
            float4 a0 = sacc[lane];
            float4 a1 = sacc[lane + 64];
            float4 a2 = sacc[lane + 128];
            float4 a3 = sacc[lane + 192];
            float4 out;
            out.x = Z * (a0.x + a1.x + a2.x + a3.x);
            out.y = Z * (a0.y + a1.y + a2.y + a3.y);
            out.z = Z * (a0.z + a1.z + a2.z + a3.z);
            out.w = Z * (a0.w + a1.w + a2.w + a3.w);
            V4[m4] = out;
        }
        __syncthreads();
    }
}

extern "C" void kernel_launch(void* const* d_in, const int* in_sizes, int n_in,
                              void* d_out, int out_size)
{
    const float* q  = (const float*)d_in[0];
    const float* k  = (const float*)d_in[1];
    const float* v  = (const float*)d_in[2];
    const float* Si = (const float*)d_in[3];
    const float* Zi = (const float*)d_in[4];

    const long long nQ  = in_sizes[0];  // BN * D
    const long long nV  = in_sizes[2];  // BN * M
    const long long nSi = in_sizes[3];  // BN * D * M

    const int D  = (int)(nSi / nV);
    const int M  = (int)(nSi / nQ);
    const int BN = (int)(nQ / D);

    float* out   = (float*)d_out;
    float* outV  = out;                 // [BN, M]
    float* outSi = out + nV;            // [BN, D, M]
    float* outZi = out + nV + nSi;      // [BN, D]

    rla_kernel<<<BN, 256>>>(q, k, v, Si, Zi, outV, outSi, outZi, D, M);
}